// round 13
// baseline (speedup 1.0000x reference)
#include <cuda_runtime.h>

#define NWIN 64
#define HD   32
#define NH   6
#define ATT_SCALE 0.17677669529663687f   // 32^-0.5
#define LOG2E 1.4426950408889634f
#define WARPS_PER_CTA 6
#define NTHREADS (WARPS_PER_CTA * 32)

typedef unsigned long long u64;

// bias, paired: [h][m2][lane][4] = {b[2m][r0], b[2m][r1], b[2m+1][r0], b[2m+1][r1]}
// where r0 = lane, r1 = lane + 32, pre-scaled by log2(e)
__device__ float g_biasP[NH * NWIN * NWIN];

static __device__ __forceinline__ u64 fma2(u64 a, u64 b, u64 c) {
    u64 d;
    asm("fma.rn.f32x2 %0, %1, %2, %3;" : "=l"(d) : "l"(a), "l"(b), "l"(c));
    return d;
}
static __device__ __forceinline__ u64 add2(u64 a, u64 b) {
    u64 d;
    asm("add.rn.f32x2 %0, %1, %2;" : "=l"(d) : "l"(a), "l"(b));
    return d;
}
static __device__ __forceinline__ u64 pack2(float x, float y) {
    u64 d;
    asm("mov.b64 %0, {%1, %2};" : "=l"(d) : "f"(x), "f"(y));
    return d;
}
static __device__ __forceinline__ float2 unpack2(u64 u) {
    float2 r;
    asm("mov.b64 {%0, %1}, %2;" : "=f"(r.x), "=f"(r.y) : "l"(u));
    return r;
}
static __device__ __forceinline__ float ex2f(float x) {
    float y;
    asm("ex2.approx.ftz.f32 %0, %1;" : "=f"(y) : "f"(x));
    return y;
}

// ---------------------------------------------------------------------------
// Kernel 1: relative-position bias MLP  [64,64,2] -> g_biasP (paired layout)
// ---------------------------------------------------------------------------
__global__ void __launch_bounds__(256)
bias_kernel(const float* __restrict__ rel, const float* __restrict__ w1,
            const float* __restrict__ b1, const float* __restrict__ w2,
            const float* __restrict__ b2) {
    __shared__ float s_w1a[256];
    __shared__ float s_w1b[256];
    __shared__ float s_b1[256];
    __shared__ float s_w2[256 * NH];

    const int tid = threadIdx.x;
    s_w1a[tid] = w1[tid];
    s_w1b[tid] = w1[256 + tid];
    s_b1[tid]  = b1[tid];
#pragma unroll
    for (int i = tid; i < 256 * NH; i += 256) s_w2[i] = w2[i];
    __syncthreads();

    const int idx = blockIdx.x * 256 + tid;  // r*64 + m
    const float r0 = rel[idx * 2 + 0];
    const float r1 = rel[idx * 2 + 1];

    float acc[NH];
#pragma unroll
    for (int o = 0; o < NH; o++) acc[o] = 0.0f;

#pragma unroll 4
    for (int hh = 0; hh < 256; hh++) {
        float a = fmaf(r0, s_w1a[hh], fmaf(r1, s_w1b[hh], s_b1[hh]));
        a = fmaxf(a, 0.0f);
#pragma unroll
        for (int o = 0; o < NH; o++) acc[o] = fmaf(a, s_w2[hh * NH + o], acc[o]);
    }
    const int r = idx >> 6;
    const int m = idx & 63;
    // paired index: [m>>1][lane = r&31][ (m&1)*2 + (r>>5) ]
    const int pi = (m >> 1) * 128 + (r & 31) * 4 + (m & 1) * 2 + (r >> 5);
#pragma unroll
    for (int o = 0; o < NH; o++)
        g_biasP[o * 4096 + pi] = (acc[o] + b2[o]) * LOG2E;
}

// ---------------------------------------------------------------------------
// Kernel 2: one WARP = one (b,h) window. Lane owns query rows {lane, lane+32}.
//   k[m]/v[m] rows from per-warp smem via broadcast LDS.128.
//   Streaming softmax (no max subtraction; fp32 range is ample).
//   Loop over m-pairs; one LDS.128 brings bias for both m's.
// ---------------------------------------------------------------------------
__global__ void __launch_bounds__(NTHREADS, 2)
attn_kernel(const float* __restrict__ qkv, float* __restrict__ out) {
    extern __shared__ float smem[];
    float* sbias = smem;  // 4096 floats, shared by all warps (same h)

    const int tid  = threadIdx.x;
    const int lane = tid & 31;
    const int w    = tid >> 5;
    const int h    = blockIdx.x;
    const int b    = blockIdx.y * WARPS_PER_CTA + w;
    const bool active = (b < 2048);

    float* sk = smem + 4096 + w * 4096;  // 64 x 32
    float* sv = sk + 2048;               // 64 x 32

    // ---- stage bias tile (all threads participate) ----------------------
    {
        const float4* gb = (const float4*)(g_biasP + h * 4096);
#pragma unroll
        for (int i = tid; i < 1024; i += NTHREADS)
            ((float4*)sbias)[i] = gb[i];
    }

    // ---- stage k, v into per-warp smem + q rows into registers ----------
    ulonglong2 q0[8], q1[8];
    if (active) {
        const float* base = qkv + (size_t)b * (NWIN * 576) + h * HD;
        const int r4 = lane >> 3;  // 0..3
        const int f  = lane & 7;   // 0..7
#pragma unroll
        for (int i = 0; i < 16; i++) {
            const int n = i * 4 + r4;
            const float* g = base + n * 576 + f * 4;
            float4 kx = *(const float4*)(g + 192);
            float4 vx = *(const float4*)(g + 384);
            *(float4*)(sk + n * 32 + f * 4) = kx;
            *(float4*)(sv + n * 32 + f * 4) = vx;
        }
        const float* qr0 = base + lane * 576;
        const float* qr1 = base + (lane + 32) * 576;
#pragma unroll
        for (int i = 0; i < 8; i++) {
            q0[i] = *(const ulonglong2*)(qr0 + i * 4);
            q1[i] = *(const ulonglong2*)(qr1 + i * 4);
        }
    }
    __syncthreads();
    if (!active) return;

    // ---- streaming attention over key-index pairs ------------------------
    u64 o0[16], o1[16];
#pragma unroll
    for (int j = 0; j < 16; j++) { o0[j] = 0ull; o1[j] = 0ull; }
    u64 sums = 0ull;  // (sum row0, sum row1)

    // paired-bias base for this lane: float index 4*lane within each
    // 128-float (= 32 ulonglong2) m2-block
    const ulonglong2* bias_l = (const ulonglong2*)(sbias + 4 * lane);

#pragma unroll 1
    for (int m2 = 0; m2 < NWIN / 2; m2++) {
        const ulonglong2 bpair = bias_l[m2 * 32];  // {b(2m,r0),b(2m,r1)},{b(2m+1,r0),b(2m+1,r1)}

#pragma unroll
        for (int half = 0; half < 2; half++) {
            const int m = 2 * m2 + half;
            const ulonglong2* krow = (const ulonglong2*)(sk + m * 32);
            const ulonglong2* vrow = (const ulonglong2*)(sv + m * 32);

            // dot products (packed over d): 4 chains of depth 8
            u64 d0a = 0ull, d0b = 0ull, d1a = 0ull, d1b = 0ull;
#pragma unroll
            for (int j = 0; j < 8; j += 2) {
                ulonglong2 ka = krow[j];
                ulonglong2 kb = krow[j + 1];
                d0a = fma2(q0[j].x, ka.x, d0a);
                d0b = fma2(q0[j].y, ka.y, d0b);
                d1a = fma2(q1[j].x, ka.x, d1a);
                d1b = fma2(q1[j].y, ka.y, d1b);
                d0a = fma2(q0[j + 1].x, kb.x, d0a);
                d0b = fma2(q0[j + 1].y, kb.y, d0b);
                d1a = fma2(q1[j + 1].x, kb.x, d1a);
                d1b = fma2(q1[j + 1].y, kb.y, d1b);
            }
            float2 bf = unpack2(half == 0 ? bpair.x : bpair.y);  // log2e-scaled
            float2 p0 = unpack2(add2(d0a, d0b));
            float2 p1 = unpack2(add2(d1a, d1b));
            float e0 = ex2f(fmaf(p0.x + p0.y, ATT_SCALE * LOG2E, bf.x));
            float e1 = ex2f(fmaf(p1.x + p1.y, ATT_SCALE * LOG2E, bf.y));
            sums = add2(sums, pack2(e0, e1));
            const u64 e0p = pack2(e0, e0);
            const u64 e1p = pack2(e1, e1);

#pragma unroll
            for (int j = 0; j < 8; j++) {
                ulonglong2 vx = vrow[j];
                o0[2 * j]     = fma2(e0p, vx.x, o0[2 * j]);
                o0[2 * j + 1] = fma2(e0p, vx.y, o0[2 * j + 1]);
                o1[2 * j]     = fma2(e1p, vx.x, o1[2 * j]);
                o1[2 * j + 1] = fma2(e1p, vx.y, o1[2 * j + 1]);
            }
        }
    }

    // ---- epilogue: normalize + store ------------------------------------
    float2 s = unpack2(sums);
    const float inv0 = 1.0f / s.x;
    const float inv1 = 1.0f / s.y;

    float* orow0 = out + (size_t)b * (NWIN * 192) + lane * 192 + h * HD;
    float* orow1 = orow0 + 32 * 192;
#pragma unroll
    for (int j = 0; j < 8; j++) {
        float2 a0 = unpack2(o0[2 * j]);
        float2 a1 = unpack2(o0[2 * j + 1]);
        *(float4*)(orow0 + 4 * j) =
            make_float4(a0.x * inv0, a0.y * inv0, a1.x * inv0, a1.y * inv0);
        float2 c0 = unpack2(o1[2 * j]);
        float2 c1 = unpack2(o1[2 * j + 1]);
        *(float4*)(orow1 + 4 * j) =
            make_float4(c0.x * inv1, c0.y * inv1, c1.x * inv1, c1.y * inv1);
    }
}

// ---------------------------------------------------------------------------
extern "C" void kernel_launch(void* const* d_in, const int* in_sizes, int n_in,
                              void* d_out, int out_size) {
    const float* qkv = (const float*)d_in[0];
    const float* rel = (const float*)d_in[1];
    const float* w1  = (const float*)d_in[2];
    const float* b1  = (const float*)d_in[3];
    const float* w2  = (const float*)d_in[4];
    const float* b2  = (const float*)d_in[5];
    float* out = (float*)d_out;

    const int smem_bytes = (4096 + WARPS_PER_CTA * 4096) * sizeof(float);  // 112 KB
    cudaFuncSetAttribute(attn_kernel, cudaFuncAttributeMaxDynamicSharedMemorySize,
                         smem_bytes);

    bias_kernel<<<16, 256>>>(rel, w1, b1, w2, b2);
    const int gy = (2048 + WARPS_PER_CTA - 1) / WARPS_PER_CTA;  // 342
    attn_kernel<<<dim3(NH, gy), NTHREADS, smem_bytes>>>(qkv, out);
}

// round 14
// speedup vs baseline: 1.1303x; 1.1303x over previous
#include <cuda_runtime.h>

#define NWIN 64
#define HD   32
#define NH   6
#define ATT_SCALE 0.17677669529663687f   // 32^-0.5
#define LOG2E 1.4426950408889634f
#define WARPS_PER_CTA 6
#define NTHREADS (WARPS_PER_CTA * 32)

typedef unsigned long long u64;

// bias, paired: [h][m2][lane][4] = {b[2m][r0], b[2m][r1], b[2m+1][r0], b[2m+1][r1]}
// where r0 = lane, r1 = lane + 32, pre-scaled by log2(e)
__device__ float g_biasP[NH * NWIN * NWIN];

static __device__ __forceinline__ u64 fma2(u64 a, u64 b, u64 c) {
    u64 d;
    asm("fma.rn.f32x2 %0, %1, %2, %3;" : "=l"(d) : "l"(a), "l"(b), "l"(c));
    return d;
}
static __device__ __forceinline__ u64 add2(u64 a, u64 b) {
    u64 d;
    asm("add.rn.f32x2 %0, %1, %2;" : "=l"(d) : "l"(a), "l"(b));
    return d;
}
static __device__ __forceinline__ u64 pack2(float x, float y) {
    u64 d;
    asm("mov.b64 %0, {%1, %2};" : "=l"(d) : "f"(x), "f"(y));
    return d;
}
static __device__ __forceinline__ float2 unpack2(u64 u) {
    float2 r;
    asm("mov.b64 {%0, %1}, %2;" : "=f"(r.x), "=f"(r.y) : "l"(u));
    return r;
}
static __device__ __forceinline__ float ex2f(float x) {
    float y;
    asm("ex2.approx.ftz.f32 %0, %1;" : "=f"(y) : "f"(x));
    return y;
}

// ---------------------------------------------------------------------------
// Kernel 1: relative-position bias MLP  [64,64,2] -> g_biasP (paired layout)
// ---------------------------------------------------------------------------
__global__ void __launch_bounds__(256)
bias_kernel(const float* __restrict__ rel, const float* __restrict__ w1,
            const float* __restrict__ b1, const float* __restrict__ w2,
            const float* __restrict__ b2) {
    __shared__ float s_w1a[256];
    __shared__ float s_w1b[256];
    __shared__ float s_b1[256];
    __shared__ float s_w2[256 * NH];

    const int tid = threadIdx.x;
    s_w1a[tid] = w1[tid];
    s_w1b[tid] = w1[256 + tid];
    s_b1[tid]  = b1[tid];
#pragma unroll
    for (int i = tid; i < 256 * NH; i += 256) s_w2[i] = w2[i];
    __syncthreads();

    const int idx = blockIdx.x * 256 + tid;  // r*64 + m
    const float r0 = rel[idx * 2 + 0];
    const float r1 = rel[idx * 2 + 1];

    float acc[NH];
#pragma unroll
    for (int o = 0; o < NH; o++) acc[o] = 0.0f;

#pragma unroll 4
    for (int hh = 0; hh < 256; hh++) {
        float a = fmaf(r0, s_w1a[hh], fmaf(r1, s_w1b[hh], s_b1[hh]));
        a = fmaxf(a, 0.0f);
#pragma unroll
        for (int o = 0; o < NH; o++) acc[o] = fmaf(a, s_w2[hh * NH + o], acc[o]);
    }
    const int r = idx >> 6;
    const int m = idx & 63;
    // paired index: [m>>1][lane = r&31][ (m&1)*2 + (r>>5) ]
    const int pi = (m >> 1) * 128 + (r & 31) * 4 + (m & 1) * 2 + (r >> 5);
#pragma unroll
    for (int o = 0; o < NH; o++)
        g_biasP[o * 4096 + pi] = (acc[o] + b2[o]) * LOG2E;
}

// ---------------------------------------------------------------------------
// Kernel 2: one WARP = one (b,h) window, fully independent — NO __syncthreads.
//   Lane owns query rows {lane, lane+32}. k/v rows from this warp's own smem
//   region via broadcast LDS.128. Bias read straight from gmem (__ldg float4
//   per 2 m, L1D/L2 cached, heavy per-SM reuse). Streaming softmax.
// ---------------------------------------------------------------------------
__global__ void __launch_bounds__(NTHREADS, 2)
attn_kernel(const float* __restrict__ qkv, float* __restrict__ out) {
    extern __shared__ float smem[];

    const int tid  = threadIdx.x;
    const int lane = tid & 31;
    const int w    = tid >> 5;
    const int h    = blockIdx.x;
    const int b    = blockIdx.y * WARPS_PER_CTA + w;
    if (b >= 2048) return;

    float* sk = smem + w * 4096;   // 64 x 32
    float* sv = sk + 2048;         // 64 x 32

    // ---- stage k, v into this warp's smem + q rows into registers -------
    const float* base = qkv + (size_t)b * (NWIN * 576) + h * HD;
    {
        const int r4 = lane >> 3;  // 0..3
        const int f  = lane & 7;   // 0..7
#pragma unroll
        for (int i = 0; i < 16; i++) {
            const int n = i * 4 + r4;
            const float* g = base + n * 576 + f * 4;
            float4 kx = *(const float4*)(g + 192);
            float4 vx = *(const float4*)(g + 384);
            *(float4*)(sk + n * 32 + f * 4) = kx;
            *(float4*)(sv + n * 32 + f * 4) = vx;
        }
    }
    ulonglong2 q0[8], q1[8];
    {
        const float* qr0 = base + lane * 576;
        const float* qr1 = base + (lane + 32) * 576;
#pragma unroll
        for (int i = 0; i < 8; i++) {
            q0[i] = *(const ulonglong2*)(qr0 + i * 4);
            q1[i] = *(const ulonglong2*)(qr1 + i * 4);
        }
    }
    __syncwarp();

    // ---- streaming attention over key-index pairs ------------------------
    u64 o0[16], o1[16];
#pragma unroll
    for (int j = 0; j < 16; j++) { o0[j] = 0ull; o1[j] = 0ull; }
    u64 sums = 0ull;  // (sum row0, sum row1)

    // paired-bias base for this lane (gmem, cached)
    const float4* bias_l = (const float4*)(g_biasP + h * 4096 + 4 * lane);

#pragma unroll 1
    for (int m2 = 0; m2 < NWIN / 2; m2++) {
        const float4 bp = __ldg(bias_l + m2 * 32);  // {b(2m,r0),b(2m,r1),b(2m+1,r0),b(2m+1,r1)}

#pragma unroll
        for (int half = 0; half < 2; half++) {
            const int m = 2 * m2 + half;
            const ulonglong2* krow = (const ulonglong2*)(sk + m * 32);
            const ulonglong2* vrow = (const ulonglong2*)(sv + m * 32);

            // dot products (packed over d): 4 chains of depth 8
            u64 d0a = 0ull, d0b = 0ull, d1a = 0ull, d1b = 0ull;
#pragma unroll
            for (int j = 0; j < 8; j += 2) {
                ulonglong2 ka = krow[j];
                ulonglong2 kb = krow[j + 1];
                d0a = fma2(q0[j].x, ka.x, d0a);
                d0b = fma2(q0[j].y, ka.y, d0b);
                d1a = fma2(q1[j].x, ka.x, d1a);
                d1b = fma2(q1[j].y, ka.y, d1b);
                d0a = fma2(q0[j + 1].x, kb.x, d0a);
                d0b = fma2(q0[j + 1].y, kb.y, d0b);
                d1a = fma2(q1[j + 1].x, kb.x, d1a);
                d1b = fma2(q1[j + 1].y, kb.y, d1b);
            }
            const float bfx = half == 0 ? bp.x : bp.z;  // log2e-scaled
            const float bfy = half == 0 ? bp.y : bp.w;
            float2 p0 = unpack2(add2(d0a, d0b));
            float2 p1 = unpack2(add2(d1a, d1b));
            float e0 = ex2f(fmaf(p0.x + p0.y, ATT_SCALE * LOG2E, bfx));
            float e1 = ex2f(fmaf(p1.x + p1.y, ATT_SCALE * LOG2E, bfy));
            sums = add2(sums, pack2(e0, e1));
            const u64 e0p = pack2(e0, e0);
            const u64 e1p = pack2(e1, e1);

#pragma unroll
            for (int j = 0; j < 8; j++) {
                ulonglong2 vx = vrow[j];
                o0[2 * j]     = fma2(e0p, vx.x, o0[2 * j]);
                o0[2 * j + 1] = fma2(e0p, vx.y, o0[2 * j + 1]);
                o1[2 * j]     = fma2(e1p, vx.x, o1[2 * j]);
                o1[2 * j + 1] = fma2(e1p, vx.y, o1[2 * j + 1]);
            }
        }
    }

    // ---- epilogue: normalize + store ------------------------------------
    float2 s = unpack2(sums);
    const float inv0 = 1.0f / s.x;
    const float inv1 = 1.0f / s.y;

    float* orow0 = out + (size_t)b * (NWIN * 192) + lane * 192 + h * HD;
    float* orow1 = orow0 + 32 * 192;
#pragma unroll
    for (int j = 0; j < 8; j++) {
        float2 a0 = unpack2(o0[2 * j]);
        float2 a1 = unpack2(o0[2 * j + 1]);
        *(float4*)(orow0 + 4 * j) =
            make_float4(a0.x * inv0, a0.y * inv0, a1.x * inv0, a1.y * inv0);
        float2 c0 = unpack2(o1[2 * j]);
        float2 c1 = unpack2(o1[2 * j + 1]);
        *(float4*)(orow1 + 4 * j) =
            make_float4(c0.x * inv1, c0.y * inv1, c1.x * inv1, c1.y * inv1);
    }
}

// ---------------------------------------------------------------------------
extern "C" void kernel_launch(void* const* d_in, const int* in_sizes, int n_in,
                              void* d_out, int out_size) {
    const float* qkv = (const float*)d_in[0];
    const float* rel = (const float*)d_in[1];
    const float* w1  = (const float*)d_in[2];
    const float* b1  = (const float*)d_in[3];
    const float* w2  = (const float*)d_in[4];
    const float* b2  = (const float*)d_in[5];
    float* out = (float*)d_out;

    const int smem_bytes = WARPS_PER_CTA * 4096 * sizeof(float);  // 96 KB
    cudaFuncSetAttribute(attn_kernel, cudaFuncAttributeMaxDynamicSharedMemorySize,
                         smem_bytes);

    bias_kernel<<<16, 256>>>(rel, w1, b1, w2, b2);
    const int gy = (2048 + WARPS_PER_CTA - 1) / WARPS_PER_CTA;  // 342
    attn_kernel<<<dim3(NH, gy), NTHREADS, smem_bytes>>>(qkv, out);
}

// round 15
// speedup vs baseline: 1.1344x; 1.0036x over previous
#include <cuda_runtime.h>

#define NWIN 64
#define HD   32
#define NH   6
#define ATT_SCALE 0.17677669529663687f   // 32^-0.5
#define LOG2E 1.4426950408889634f
#define WARPS_PER_CTA 6
#define NTHREADS (WARPS_PER_CTA * 32)

typedef unsigned long long u64;

// bias, paired: [h][m2][lane][4] = {b[2m][r0], b[2m][r1], b[2m+1][r0], b[2m+1][r1]}
// where r0 = lane, r1 = lane + 32, pre-scaled by log2(e)
__device__ float g_biasP[NH * NWIN * NWIN];

static __device__ __forceinline__ u64 fma2(u64 a, u64 b, u64 c) {
    u64 d;
    asm("fma.rn.f32x2 %0, %1, %2, %3;" : "=l"(d) : "l"(a), "l"(b), "l"(c));
    return d;
}
static __device__ __forceinline__ u64 add2(u64 a, u64 b) {
    u64 d;
    asm("add.rn.f32x2 %0, %1, %2;" : "=l"(d) : "l"(a), "l"(b));
    return d;
}
static __device__ __forceinline__ u64 pack2(float x, float y) {
    u64 d;
    asm("mov.b64 %0, {%1, %2};" : "=l"(d) : "f"(x), "f"(y));
    return d;
}
static __device__ __forceinline__ float2 unpack2(u64 u) {
    float2 r;
    asm("mov.b64 {%0, %1}, %2;" : "=f"(r.x), "=f"(r.y) : "l"(u));
    return r;
}
static __device__ __forceinline__ float ex2f(float x) {
    float y;
    asm("ex2.approx.ftz.f32 %0, %1;" : "=f"(y) : "f"(x));
    return y;
}

// ---------------------------------------------------------------------------
// Kernel 1: relative-position bias MLP  [64,64,2] -> g_biasP (paired layout)
// ---------------------------------------------------------------------------
__global__ void __launch_bounds__(256)
bias_kernel(const float* __restrict__ rel, const float* __restrict__ w1,
            const float* __restrict__ b1, const float* __restrict__ w2,
            const float* __restrict__ b2) {
    __shared__ float s_w1a[256];
    __shared__ float s_w1b[256];
    __shared__ float s_b1[256];
    __shared__ float s_w2[256 * NH];

    const int tid = threadIdx.x;
    s_w1a[tid] = w1[tid];
    s_w1b[tid] = w1[256 + tid];
    s_b1[tid]  = b1[tid];
#pragma unroll
    for (int i = tid; i < 256 * NH; i += 256) s_w2[i] = w2[i];
    __syncthreads();

    const int idx = blockIdx.x * 256 + tid;  // r*64 + m
    const float r0 = rel[idx * 2 + 0];
    const float r1 = rel[idx * 2 + 1];

    float acc[NH];
#pragma unroll
    for (int o = 0; o < NH; o++) acc[o] = 0.0f;

#pragma unroll 4
    for (int hh = 0; hh < 256; hh++) {
        float a = fmaf(r0, s_w1a[hh], fmaf(r1, s_w1b[hh], s_b1[hh]));
        a = fmaxf(a, 0.0f);
#pragma unroll
        for (int o = 0; o < NH; o++) acc[o] = fmaf(a, s_w2[hh * NH + o], acc[o]);
    }
    const int r = idx >> 6;
    const int m = idx & 63;
    // paired index: [m>>1][lane = r&31][ (m&1)*2 + (r>>5) ]
    const int pi = (m >> 1) * 128 + (r & 31) * 4 + (m & 1) * 2 + (r >> 5);
#pragma unroll
    for (int o = 0; o < NH; o++)
        g_biasP[o * 4096 + pi] = (acc[o] + b2[o]) * LOG2E;
}

// ---------------------------------------------------------------------------
// Kernel 2: one WARP = one (b,h) window, fully independent — NO __syncthreads.
//   Lane owns query rows {lane, lane+32}. k/v rows from this warp's own smem
//   region via broadcast LDS.128. Bias read straight from gmem (__ldg float4
//   per 2 m, L1D/L2 cached, heavy per-SM reuse). Streaming softmax.
// ---------------------------------------------------------------------------
__global__ void __launch_bounds__(NTHREADS, 2)
attn_kernel(const float* __restrict__ qkv, float* __restrict__ out) {
    extern __shared__ float smem[];

    const int tid  = threadIdx.x;
    const int lane = tid & 31;
    const int w    = tid >> 5;
    const int h    = blockIdx.x;
    const int b    = blockIdx.y * WARPS_PER_CTA + w;
    if (b >= 2048) return;

    float* sk = smem + w * 4096;   // 64 x 32
    float* sv = sk + 2048;         // 64 x 32

    // ---- stage k, v into this warp's smem + q rows into registers -------
    const float* base = qkv + (size_t)b * (NWIN * 576) + h * HD;
    {
        const int r4 = lane >> 3;  // 0..3
        const int f  = lane & 7;   // 0..7
#pragma unroll
        for (int i = 0; i < 16; i++) {
            const int n = i * 4 + r4;
            const float* g = base + n * 576 + f * 4;
            float4 kx = *(const float4*)(g + 192);
            float4 vx = *(const float4*)(g + 384);
            *(float4*)(sk + n * 32 + f * 4) = kx;
            *(float4*)(sv + n * 32 + f * 4) = vx;
        }
    }
    ulonglong2 q0[8], q1[8];
    {
        const float* qr0 = base + lane * 576;
        const float* qr1 = base + (lane + 32) * 576;
#pragma unroll
        for (int i = 0; i < 8; i++) {
            q0[i] = *(const ulonglong2*)(qr0 + i * 4);
            q1[i] = *(const ulonglong2*)(qr1 + i * 4);
        }
    }
    __syncwarp();

    // ---- streaming attention over key-index pairs ------------------------
    u64 o0[16], o1[16];
#pragma unroll
    for (int j = 0; j < 16; j++) { o0[j] = 0ull; o1[j] = 0ull; }
    u64 sums = 0ull;  // (sum row0, sum row1)

    // paired-bias base for this lane (gmem, cached)
    const float4* bias_l = (const float4*)(g_biasP + h * 4096 + 4 * lane);

#pragma unroll 1
    for (int m2 = 0; m2 < NWIN / 2; m2++) {
        const float4 bp = __ldg(bias_l + m2 * 32);  // {b(2m,r0),b(2m,r1),b(2m+1,r0),b(2m+1,r1)}

#pragma unroll
        for (int half = 0; half < 2; half++) {
            const int m = 2 * m2 + half;
            const ulonglong2* krow = (const ulonglong2*)(sk + m * 32);
            const ulonglong2* vrow = (const ulonglong2*)(sv + m * 32);

            // dot products (packed over d): 4 chains of depth 8
            u64 d0a = 0ull, d0b = 0ull, d1a = 0ull, d1b = 0ull;
#pragma unroll
            for (int j = 0; j < 8; j += 2) {
                ulonglong2 ka = krow[j];
                ulonglong2 kb = krow[j + 1];
                d0a = fma2(q0[j].x, ka.x, d0a);
                d0b = fma2(q0[j].y, ka.y, d0b);
                d1a = fma2(q1[j].x, ka.x, d1a);
                d1b = fma2(q1[j].y, ka.y, d1b);
                d0a = fma2(q0[j + 1].x, kb.x, d0a);
                d0b = fma2(q0[j + 1].y, kb.y, d0b);
                d1a = fma2(q1[j + 1].x, kb.x, d1a);
                d1b = fma2(q1[j + 1].y, kb.y, d1b);
            }
            const float bfx = half == 0 ? bp.x : bp.z;  // log2e-scaled
            const float bfy = half == 0 ? bp.y : bp.w;
            float2 p0 = unpack2(add2(d0a, d0b));
            float2 p1 = unpack2(add2(d1a, d1b));
            float e0 = ex2f(fmaf(p0.x + p0.y, ATT_SCALE * LOG2E, bfx));
            float e1 = ex2f(fmaf(p1.x + p1.y, ATT_SCALE * LOG2E, bfy));
            sums = add2(sums, pack2(e0, e1));
            const u64 e0p = pack2(e0, e0);
            const u64 e1p = pack2(e1, e1);

#pragma unroll
            for (int j = 0; j < 8; j++) {
                ulonglong2 vx = vrow[j];
                o0[2 * j]     = fma2(e0p, vx.x, o0[2 * j]);
                o0[2 * j + 1] = fma2(e0p, vx.y, o0[2 * j + 1]);
                o1[2 * j]     = fma2(e1p, vx.x, o1[2 * j]);
                o1[2 * j + 1] = fma2(e1p, vx.y, o1[2 * j + 1]);
            }
        }
    }

    // ---- epilogue: normalize + store ------------------------------------
    float2 s = unpack2(sums);
    const float inv0 = 1.0f / s.x;
    const float inv1 = 1.0f / s.y;

    float* orow0 = out + (size_t)b * (NWIN * 192) + lane * 192 + h * HD;
    float* orow1 = orow0 + 32 * 192;
#pragma unroll
    for (int j = 0; j < 8; j++) {
        float2 a0 = unpack2(o0[2 * j]);
        float2 a1 = unpack2(o0[2 * j + 1]);
        *(float4*)(orow0 + 4 * j) =
            make_float4(a0.x * inv0, a0.y * inv0, a1.x * inv0, a1.y * inv0);
        float2 c0 = unpack2(o1[2 * j]);
        float2 c1 = unpack2(o1[2 * j + 1]);
        *(float4*)(orow1 + 4 * j) =
            make_float4(c0.x * inv1, c0.y * inv1, c1.x * inv1, c1.y * inv1);
    }
}

// ---------------------------------------------------------------------------
extern "C" void kernel_launch(void* const* d_in, const int* in_sizes, int n_in,
                              void* d_out, int out_size) {
    const float* qkv = (const float*)d_in[0];
    const float* rel = (const float*)d_in[1];
    const float* w1  = (const float*)d_in[2];
    const float* b1  = (const float*)d_in[3];
    const float* w2  = (const float*)d_in[4];
    const float* b2  = (const float*)d_in[5];
    float* out = (float*)d_out;

    const int smem_bytes = WARPS_PER_CTA * 4096 * sizeof(float);  // 96 KB
    cudaFuncSetAttribute(attn_kernel, cudaFuncAttributeMaxDynamicSharedMemorySize,
                         smem_bytes);

    bias_kernel<<<16, 256>>>(rel, w1, b1, w2, b2);
    const int gy = (2048 + WARPS_PER_CTA - 1) / WARPS_PER_CTA;  // 342
    attn_kernel<<<dim3(NH, gy), NTHREADS, smem_bytes>>>(qkv, out);
}